// round 5
// baseline (speedup 1.0000x reference)
#include <cuda_runtime.h>

// CombineModel_wo_net_20031727468607 — GB300 sm_103a
// HBM-bound per-batch reduction (bright count, dark count, gray sum) over
// [16,3,544,960] fp32 + O(16) scalar epilogue. Roofline floor ~16 us DRAM-fed,
// ~9-13 us if the 100 MB input goes L2-resident across graph replays (L2 is
// 126 MB and not flushed per launch — hence default-policy loads, NO .cs).
// 2-kernel graph: reduce (per-block partials, no atomics/init) + finalize.

#define NB   16
#define NC   3
#define HH   544
#define WW   960
#define HWP  (HH * WW)          // 522240 pixels per channel
#define HW4  (HWP / 4)          // 130560 float4 groups per channel
#define BLOCKS_PER_BATCH 64
#define THREADS 256
#define NPART (NB * BLOCKS_PER_BATCH)   // 1024 partial slots

// Per-block partials (scratch: device globals; every slot written each run,
// so no zero-init kernel is needed and results are bit-deterministic).
__device__ float g_pb[NPART];   // bright partials
__device__ float g_pd[NPART];   // dark partials
__device__ float g_ps[NPART];   // sum partials

__global__ __launch_bounds__(THREADS) void reduce_kernel(const float* __restrict__ img) {
    const int b = blockIdx.y;
    const float4* __restrict__ cr = (const float4*)(img + (size_t)b * NC * HWP);
    const float4* __restrict__ cg = cr + HW4;
    const float4* __restrict__ cb = cr + 2 * HW4;

    float nb = 0.0f;   // bright count
    float nd = 0.0f;   // dark count
    float sm = 0.0f;   // gray sum

    const int stride = BLOCKS_PER_BATCH * THREADS;   // 16384
    int i = blockIdx.x * THREADS + threadIdx.x;

    // ~7.97 iterations/thread; unroll to front-batch LDG.128s (high MLP).
    #pragma unroll 8
    for (; i < HW4; i += stride) {
        float4 r = cr[i];
        float4 g = cg[i];
        float4 v = cb[i];
        float p0 = (r.x + g.x + v.x) * (1.0f / 3.0f);
        float p1 = (r.y + g.y + v.y) * (1.0f / 3.0f);
        float p2 = (r.z + g.z + v.z) * (1.0f / 3.0f);
        float p3 = (r.w + g.w + v.w) * (1.0f / 3.0f);

        sm += (p0 + p1) + (p2 + p3);

        nb += (p0 >= 0.75f && p0 <= 1.0f) ? 1.0f : 0.0f;
        nb += (p1 >= 0.75f && p1 <= 1.0f) ? 1.0f : 0.0f;
        nb += (p2 >= 0.75f && p2 <= 1.0f) ? 1.0f : 0.0f;
        nb += (p3 >= 0.75f && p3 <= 1.0f) ? 1.0f : 0.0f;

        nd += (p0 >= 0.0f && p0 < 0.25f) ? 1.0f : 0.0f;
        nd += (p1 >= 0.0f && p1 < 0.25f) ? 1.0f : 0.0f;
        nd += (p2 >= 0.0f && p2 < 0.25f) ? 1.0f : 0.0f;
        nd += (p3 >= 0.0f && p3 < 0.25f) ? 1.0f : 0.0f;
    }

    // warp reduction
    #pragma unroll
    for (int off = 16; off > 0; off >>= 1) {
        nb += __shfl_down_sync(0xFFFFFFFFu, nb, off);
        nd += __shfl_down_sync(0xFFFFFFFFu, nd, off);
        sm += __shfl_down_sync(0xFFFFFFFFu, sm, off);
    }

    __shared__ float s_nb[THREADS / 32];
    __shared__ float s_nd[THREADS / 32];
    __shared__ float s_sm[THREADS / 32];
    const int lane = threadIdx.x & 31;
    const int warp = threadIdx.x >> 5;
    if (lane == 0) {
        s_nb[warp] = nb;
        s_nd[warp] = nd;
        s_sm[warp] = sm;
    }
    __syncthreads();

    if (warp == 0) {
        nb = (lane < THREADS / 32) ? s_nb[lane] : 0.0f;
        nd = (lane < THREADS / 32) ? s_nd[lane] : 0.0f;
        sm = (lane < THREADS / 32) ? s_sm[lane] : 0.0f;
        #pragma unroll
        for (int off = 4; off > 0; off >>= 1) {
            nb += __shfl_down_sync(0xFFFFFFFFu, nb, off);
            nd += __shfl_down_sync(0xFFFFFFFFu, nd, off);
            sm += __shfl_down_sync(0xFFFFFFFFu, sm, off);
        }
        if (lane == 0) {
            const int slot = b * BLOCKS_PER_BATCH + blockIdx.x;
            g_pb[slot] = nb;
            g_pd[slot] = nd;
            g_ps[slot] = sm;
        }
    }
}

// Single block, 512 threads = 16 warps; warp w reduces batch w's 64 partials.
__global__ __launch_bounds__(512) void finalize_kernel(const float* __restrict__ e1,
                                                       const float* __restrict__ e2,
                                                       float* __restrict__ out) {
    const int tid  = threadIdx.x;
    const int warp = tid >> 5;          // batch index
    const int lane = tid & 31;

    __shared__ float s_dr[NB];
    __shared__ float s_avg[NB];
    __shared__ float s_gap[NB];

    {
        const int base = warp * BLOCKS_PER_BATCH;
        float nb = g_pb[base + lane] + g_pb[base + lane + 32];
        float nd = g_pd[base + lane] + g_pd[base + lane + 32];
        float sm = g_ps[base + lane] + g_ps[base + lane + 32];
        #pragma unroll
        for (int off = 16; off > 0; off >>= 1) {
            nb += __shfl_down_sync(0xFFFFFFFFu, nb, off);
            nd += __shfl_down_sync(0xFFFFFFFFu, nd, off);
            sm += __shfl_down_sync(0xFFFFFFFFu, sm, off);
        }
        if (lane == 0) {
            float dr  = nb / (nd + 1e-5f);
            float avg = sm / (float)HWP;

            // jnp.select: first matching condition wins, default 0.
            float gap;
            if (dr > 1.0f && avg > 0.4f && avg < 0.6f)       gap = 0.5f * 2.0f;
            else if (avg <= 0.3f)                            gap = 0.5f * 0.5f;
            else if (avg >= 0.7f)                            gap = 0.5f * 0.5f;
            else if (dr <= 1.0f && avg > 0.3f && avg < 0.7f) gap = 0.5f * 0.75f;
            else                                             gap = 0.0f;

            s_dr[warp]  = dr;
            s_avg[warp] = avg;
            s_gap[warp] = gap;
        }
    }
    __syncthreads();

    if (tid < NB) {
        const int b = tid;
        out[0 * NB + b] = s_dr[b];
        out[1 * NB + b] = s_avg[b];
        out[2 * NB + b] = s_gap[b];

        // Only the LAST batch element's branch/gap drives e1/e2 (reference quirk).
        const float bl = s_avg[NB - 1];
        const float gl = s_gap[NB - 1];
        const float be1 = e1[b];
        const float be2 = e2[b];
        float ne1, ne2;
        if (bl <= 0.25f) {
            ne1 = be1 + 0.5f * gl * 1.7f;
            ne2 = be2 + 0.5f * gl * 1.7f;
        } else if (bl >= 0.75f) {
            ne1 = be1 - 0.5f * gl * 1.7f;
            ne2 = be2 - 0.5f * gl * 1.7f;
        } else {
            ne1 = be1 - 0.3f * gl;
            ne2 = be2 + 0.7f * gl;
        }
        out[3 * NB + b] = ne1;
        out[4 * NB + b] = ne2;
    }
}

extern "C" void kernel_launch(void* const* d_in, const int* in_sizes, int n_in,
                              void* d_out, int out_size) {
    const float* img = (const float*)d_in[0];
    const float* e1  = (const float*)d_in[1];
    const float* e2  = (const float*)d_in[2];
    float* out = (float*)d_out;

    dim3 grid(BLOCKS_PER_BATCH, NB);
    reduce_kernel<<<grid, THREADS>>>(img);
    finalize_kernel<<<1, 512>>>(e1, e2, out);
}